// round 7
// baseline (speedup 1.0000x reference)
#include <cuda_runtime.h>
#include <math.h>

// Problem dims
#define TT   512
#define BB   256
#define OBSD 128
#define ACTD 32
#define IND  160
#define HIDD 512
#define G3D  1536
#define HFD  512

static constexpr size_t TBn = (size_t)TT * BB;      // 131072
static constexpr int NBLK = 2048;                    // reduction blocks per sum

// -------- scratch (static device globals; no runtime allocation) ----------
// g_GI holds the input-gate preacts during the recurrence (805 MB); after the
// recurrence it is dead, so the MLP hidden buffers F1/F2 alias into it.
__device__ float g_GI [TBn * G3D];   // [T*B, 1536] input-gate preacts
__device__ float g_GI0[BB  * G3D];   // special step-0 preacts
__device__ float g_HS [TBn * HIDD];  // emitted hidden states (268 MB)
__device__ float g_part[3 * NBLK];   // loss partials

__device__ __forceinline__ float4 ldg4(const float* p) {
    return *reinterpret_cast<const float4*>(p);
}
__device__ __forceinline__ float sigmoidf_(float x) { return 1.f / (1.f + expf(-x)); }

// ---------------------------------------------------------------------------
// Generic tiled SGEMM:  C[M,N] = act( A[M,K] @ W[N,K]^T + bias[N] )
//   CONCAT: A row m is [obs[m,0:128] ‖ action[m,0:32]]
//   ACTMODE: 0 = identity, 1 = ELU
// All of M,N,K are multiples of the tile params at every call site (no guards).
// ---------------------------------------------------------------------------
template<int BM, int BN, int BK, int TM, int TN, int ACTMODE, bool CONCAT>
__global__ void __launch_bounds__((BM / TM) * (BN / TN))
sgemm_k(const float* __restrict__ A, int ldA,
        const float* __restrict__ A2,
        const float* __restrict__ W, int ldW,
        const float* __restrict__ bias,
        float* __restrict__ C, int ldC,
        int K)
{
    constexpr int NT = (BM / TM) * (BN / TN);
    constexpr int KQ = BK / 4;

    __shared__ __align__(16) float As[BK][BM + 4];
    __shared__ __align__(16) float Ws[BK][BN + 4];

    const int tid = threadIdx.x;
    const int tx  = tid % (BN / TN);
    const int ty  = tid / (BN / TN);
    const int m0  = blockIdx.y * BM;
    const int n0  = blockIdx.x * BN;

    float acc[TM][TN];
#pragma unroll
    for (int i = 0; i < TM; i++)
#pragma unroll
        for (int j = 0; j < TN; j++) acc[i][j] = 0.f;

    for (int k0 = 0; k0 < K; k0 += BK) {
        // load A tile (float4 along K), store transposed into smem
        for (int i4 = tid; i4 < BM * KQ; i4 += NT) {
            int m = i4 / KQ, q = i4 % KQ;
            int kg = k0 + q * 4;
            float4 v;
            if (CONCAT) {
                if (kg < OBSD) v = ldg4(A  + (size_t)(m0 + m) * OBSD + kg);
                else           v = ldg4(A2 + (size_t)(m0 + m) * ACTD + (kg - OBSD));
            } else {
                v = ldg4(A + (size_t)(m0 + m) * ldA + kg);
            }
            As[q * 4 + 0][m] = v.x; As[q * 4 + 1][m] = v.y;
            As[q * 4 + 2][m] = v.z; As[q * 4 + 3][m] = v.w;
        }
        // load W tile
        for (int i4 = tid; i4 < BN * KQ; i4 += NT) {
            int n = i4 / KQ, q = i4 % KQ;
            int kg = k0 + q * 4;
            float4 v = ldg4(W + (size_t)(n0 + n) * ldW + kg);
            Ws[q * 4 + 0][n] = v.x; Ws[q * 4 + 1][n] = v.y;
            Ws[q * 4 + 2][n] = v.z; Ws[q * 4 + 3][n] = v.w;
        }
        __syncthreads();

#pragma unroll
        for (int kk = 0; kk < BK; kk++) {
            float a[TM], b[TN];
#pragma unroll
            for (int i = 0; i < TM; i += 4)
                *reinterpret_cast<float4*>(&a[i]) =
                    *reinterpret_cast<const float4*>(&As[kk][ty * TM + i]);
#pragma unroll
            for (int j = 0; j < TN; j += 4)
                *reinterpret_cast<float4*>(&b[j]) =
                    *reinterpret_cast<const float4*>(&Ws[kk][tx * TN + j]);
#pragma unroll
            for (int i = 0; i < TM; i++)
#pragma unroll
                for (int j = 0; j < TN; j++)
                    acc[i][j] = fmaf(a[i], b[j], acc[i][j]);
        }
        __syncthreads();
    }

#pragma unroll
    for (int i = 0; i < TM; i++) {
        size_t m = (size_t)m0 + ty * TM + i;
#pragma unroll
        for (int j = 0; j < TN; j++) {
            int n = n0 + tx * TN + j;
            float v = acc[i][j] + bias[n];
            if (ACTMODE == 1) v = (v > 0.f) ? v : expm1f(v);
            C[m * (size_t)ldC + n] = v;
        }
    }
}

// ---------------------------------------------------------------------------
// Fused GRU step:  h_next = GRU(gi_t, h_prev)
// One kernel per time step. Each CTA computes a [32 x 32] tile of h_next:
// it accumulates the three gate pre-activations (w_hh rows j, j+512, j+1024)
// over K=512, then applies the gate math in-register. Grid (16, 8) = 128 CTAs.
// ---------------------------------------------------------------------------
#define SBM 32   // batch rows per CTA
#define SBJ 32   // gate columns per CTA
#define SBK 16   // K slice

__global__ void __launch_bounds__(256)
step_k(const float* __restrict__ hp,    // h_prev  [B, 512]
       const float* __restrict__ w_hh,  // [1536, 512]
       const float* __restrict__ b_hh,  // [1536]
       const float* __restrict__ gi,    // gi_t    [B, 1536]
       float* __restrict__ ho)          // h_next  [B, 512]
{
    __shared__ __align__(16) float As[SBK][SBM + 2];
    __shared__ __align__(16) float Wr[SBK][SBJ + 2];
    __shared__ __align__(16) float Wz[SBK][SBJ + 2];
    __shared__ __align__(16) float Wn[SBK][SBJ + 2];

    const int tid = threadIdx.x;
    const int j0  = blockIdx.x * SBJ;
    const int b0  = blockIdx.y * SBM;
    const int tx  = tid & 15;   // 16 col groups (2 cols each)
    const int ty  = tid >> 4;   // 16 row groups (2 rows each)

    float ar[2][2] = {{0,0},{0,0}};
    float az[2][2] = {{0,0},{0,0}};
    float an[2][2] = {{0,0},{0,0}};

    for (int k0 = 0; k0 < HIDD; k0 += SBK) {
        // A tile: 32 rows x 16 K = 128 float4 loads (threads 0-127)
        if (tid < 128) {
            int m = tid >> 2, q = tid & 3;
            float4 v = ldg4(hp + (size_t)(b0 + m) * HIDD + k0 + q * 4);
            As[q * 4 + 0][m] = v.x; As[q * 4 + 1][m] = v.y;
            As[q * 4 + 2][m] = v.z; As[q * 4 + 3][m] = v.w;
        }
        // W tiles: 3 gates x 32 rows x 16 K = 384 float4 loads
        for (int t = tid; t < 384; t += 256) {
            int g = t >> 7, r = t & 127;
            int j = r >> 2, q = r & 3;
            float4 v = ldg4(w_hh + (size_t)(g * HIDD + j0 + j) * HIDD + k0 + q * 4);
            float (*Wg)[SBJ + 2] = (g == 0) ? Wr : (g == 1) ? Wz : Wn;
            Wg[q * 4 + 0][j] = v.x; Wg[q * 4 + 1][j] = v.y;
            Wg[q * 4 + 2][j] = v.z; Wg[q * 4 + 3][j] = v.w;
        }
        __syncthreads();

#pragma unroll
        for (int kk = 0; kk < SBK; kk++) {
            float a0 = As[kk][ty * 2], a1 = As[kk][ty * 2 + 1];
            float r0 = Wr[kk][tx * 2], r1 = Wr[kk][tx * 2 + 1];
            float z0 = Wz[kk][tx * 2], z1 = Wz[kk][tx * 2 + 1];
            float n0 = Wn[kk][tx * 2], n1 = Wn[kk][tx * 2 + 1];
            ar[0][0] = fmaf(a0, r0, ar[0][0]); ar[0][1] = fmaf(a0, r1, ar[0][1]);
            ar[1][0] = fmaf(a1, r0, ar[1][0]); ar[1][1] = fmaf(a1, r1, ar[1][1]);
            az[0][0] = fmaf(a0, z0, az[0][0]); az[0][1] = fmaf(a0, z1, az[0][1]);
            az[1][0] = fmaf(a1, z0, az[1][0]); az[1][1] = fmaf(a1, z1, az[1][1]);
            an[0][0] = fmaf(a0, n0, an[0][0]); an[0][1] = fmaf(a0, n1, an[0][1]);
            an[1][0] = fmaf(a1, n0, an[1][0]); an[1][1] = fmaf(a1, n1, an[1][1]);
        }
        __syncthreads();
    }

#pragma unroll
    for (int i = 0; i < 2; i++) {
        int m = b0 + ty * 2 + i;
        const float* gim = gi + (size_t)m * G3D;
#pragma unroll
        for (int j = 0; j < 2; j++) {
            int jg = j0 + tx * 2 + j;
            float r = sigmoidf_(gim[jg]        + ar[i][j] + b_hh[jg]);
            float z = sigmoidf_(gim[jg + 512]  + az[i][j] + b_hh[512 + jg]);
            float n = tanhf    (gim[jg + 1024] + r * (an[i][j] + b_hh[1024 + jg]));
            ho[(size_t)m * HIDD + jg] =
                (1.f - z) * n + z * hp[(size_t)m * HIDD + jg];
        }
    }
}

// step 0: h_prev = 0  =>  gh = b_hh,  h0 = (1-z)*n
__global__ void gate0_k(const float* __restrict__ gi, const float* __restrict__ bhh,
                        float* __restrict__ ho)
{
    int idx = blockIdx.x * blockDim.x + threadIdx.x;
    int b = idx >> 9, j = idx & 511;
    size_t base = (size_t)b * G3D + j;
    float r = sigmoidf_(gi[base]        + bhh[j]);
    float z = sigmoidf_(gi[base + 512]  + bhh[512 + j]);
    float n = tanhf    (gi[base + 1024] + r * bhh[1024 + j]);
    ho[idx] = (1.f - z) * n;
}

// ---------------------------------------------------------------------------
// N=1 head: pre_reward[m] = dot(F2[m,:], rw2) + rb2.  One warp per row.
// ---------------------------------------------------------------------------
__global__ void dot_k(const float* __restrict__ A, const float* __restrict__ w,
                      const float* __restrict__ bp, float* __restrict__ out)
{
    int g = blockIdx.x * blockDim.x + threadIdx.x;
    int row = g >> 5, lane = g & 31;
    const float4* a4 = reinterpret_cast<const float4*>(A + (size_t)row * HFD);
    const float4* w4 = reinterpret_cast<const float4*>(w);
    float s = 0.f;
#pragma unroll
    for (int i = lane; i < HFD / 4; i += 32) {
        float4 a = a4[i], b = w4[i];
        s += a.x * b.x + a.y * b.y + a.z * b.z + a.w * b.w;
    }
#pragma unroll
    for (int o = 16; o; o >>= 1) s += __shfl_xor_sync(0xffffffffu, s, o);
    if (lane == 0) out[row] = s + bp[0];
}

// ---------------------------------------------------------------------------
// Loss: deterministic 2-stage sum of squared residuals.
// BCAST: mu is [T*B,1] broadcast over the last (ACT=32) axis of x.
// ---------------------------------------------------------------------------
template<bool BCAST>
__global__ void reduce_sq_k(const float* __restrict__ x, const float* __restrict__ mu,
                            size_t n, float* __restrict__ part)
{
    float s = 0.f;
    for (size_t i = (size_t)blockIdx.x * blockDim.x + threadIdx.x; i < n;
         i += (size_t)gridDim.x * blockDim.x) {
        float m = BCAST ? mu[i >> 5] : mu[i];
        float d = x[i] - m;
        s += d * d;
    }
    __shared__ float sm[256];
    sm[threadIdx.x] = s; __syncthreads();
    for (int o = 128; o; o >>= 1) {
        if (threadIdx.x < o) sm[threadIdx.x] += sm[threadIdx.x + o];
        __syncthreads();
    }
    if (threadIdx.x == 0) part[blockIdx.x] = sm[0];
}

__global__ void finalize_k(const float* __restrict__ part, float* __restrict__ out)
{
    __shared__ double sm[256];
    double s = 0.0;
    for (int i = threadIdx.x; i < 3 * NBLK; i += 256) s += (double)part[i];
    sm[threadIdx.x] = s; __syncthreads();
    for (int o = 128; o; o >>= 1) {
        if (threadIdx.x < o) sm[threadIdx.x] += sm[threadIdx.x + o];
        __syncthreads();
    }
    if (threadIdx.x == 0) {
        const double LOG2PI = 1.8378770664093453;
        // loss = 0.5*S/(T*B) + 0.5*log(2pi)*(OBS + ACT + ACT)
        out[0] = (float)(0.5 * sm[0] / (double)(TT * BB)
                         + 0.5 * LOG2PI * (double)(OBSD + 2 * ACTD));
    }
}

// ---------------------------------------------------------------------------
extern "C" void kernel_launch(void* const* d_in, const int* in_sizes, int n_in,
                              void* d_out, int out_size)
{
    const float* obs    = (const float*)d_in[0];
    const float* action = (const float*)d_in[1];
    /* d_in[2] reward: unused by the reference math */
    const float* w_ih = (const float*)d_in[3];
    const float* w_hh = (const float*)d_in[4];
    const float* b_ih = (const float*)d_in[5];
    const float* b_hh = (const float*)d_in[6];
    const float* ow0 = (const float*)d_in[7],  *ob0 = (const float*)d_in[8];
    const float* ow1 = (const float*)d_in[9],  *ob1 = (const float*)d_in[10];
    const float* ow2 = (const float*)d_in[11], *ob2 = (const float*)d_in[12];
    const float* aw0 = (const float*)d_in[13], *ab0 = (const float*)d_in[14];
    const float* aw1 = (const float*)d_in[15], *ab1 = (const float*)d_in[16];
    const float* aw2 = (const float*)d_in[17], *ab2 = (const float*)d_in[18];
    const float* rw0 = (const float*)d_in[19], *rb0 = (const float*)d_in[20];
    const float* rw1 = (const float*)d_in[21], *rb1 = (const float*)d_in[22];
    const float* rw2 = (const float*)d_in[23], *rb2 = (const float*)d_in[24];

    float *GI, *GI0, *HS, *PART;
    cudaGetSymbolAddress((void**)&GI,   g_GI);
    cudaGetSymbolAddress((void**)&GI0,  g_GI0);
    cudaGetSymbolAddress((void**)&HS,   g_HS);
    cudaGetSymbolAddress((void**)&PART, g_part);
    // MLP scratch aliases the (dead after the recurrence) GI buffer.
    float* F1 = GI;
    float* F2 = GI + TBn * HFD;

    float* out      = (float*)d_out;
    float* pre_obs  = out + 1;
    float* pre_act  = pre_obs + TBn * OBSD;
    float* pre_rew  = pre_act + TBn * ACTD;

    // 1) GI = [obs‖action] @ w_ih^T + b_ih   for all T*B rows
    sgemm_k<128, 128, 8, 8, 8, 0, true><<<dim3(G3D / 128, TBn / 128), 256>>>(
        obs, 0, action, w_ih, IND, b_ih, GI, G3D, IND);

    // 2) GI0 = obs[0] @ w_ih[:, :128]^T + b_ih  (action part of x0 is zero)
    sgemm_k<64, 64, 8, 4, 4, 0, false><<<dim3(G3D / 64, BB / 64), 256>>>(
        obs, OBSD, nullptr, w_ih, IND, b_ih, GI0, G3D, OBSD);

    // 3) h0 (gh == b_hh since h_prev == 0) -> HS[0]
    gate0_k<<<(BB * HIDD) / 256, 256>>>(GI0, b_hh, HS);

    // 4) recurrence: one fused kernel per step (GEMM + gates), 511 nodes
    dim3 gStep(HIDD / SBJ, BB / SBM);   // (16, 8) = 128 CTAs
    for (int t = 0; t < TT - 1; t++) {
        step_k<<<gStep, 256>>>(
            HS + (size_t)t * BB * HIDD, w_hh, b_hh,
            GI + (size_t)t * BB * G3D,
            HS + (size_t)(t + 1) * BB * HIDD);
    }

    dim3 gH(HFD / 128, TBn / 128);
    dim3 gO(OBSD / 128, TBn / 128);
    dim3 gA(ACTD / 32, TBn / 128);

    // 5) obs head
    sgemm_k<128, 128, 8, 8, 8, 1, false><<<gH, 256>>>(HS, HIDD, nullptr, ow0, HIDD, ob0, F1, HFD, HIDD);
    sgemm_k<128, 128, 8, 8, 8, 1, false><<<gH, 256>>>(F1, HFD, nullptr, ow1, HFD, ob1, F2, HFD, HFD);
    sgemm_k<128, 128, 8, 8, 8, 0, false><<<gO, 256>>>(F2, HFD, nullptr, ow2, HFD, ob2, pre_obs, OBSD, HFD);

    // 6) action head (stop_gradient is identity in forward)
    sgemm_k<128, 128, 8, 8, 8, 1, false><<<gH, 256>>>(HS, HIDD, nullptr, aw0, HIDD, ab0, F1, HFD, HIDD);
    sgemm_k<128, 128, 8, 8, 8, 1, false><<<gH, 256>>>(F1, HFD, nullptr, aw1, HFD, ab1, F2, HFD, HFD);
    sgemm_k<128, 32, 8, 8, 4, 0, false><<<gA, 128>>>(F2, HFD, nullptr, aw2, HFD, ab2, pre_act, ACTD, HFD);

    // 7) reward head
    sgemm_k<128, 128, 8, 8, 8, 1, false><<<gH, 256>>>(HS, HIDD, nullptr, rw0, HIDD, rb0, F1, HFD, HIDD);
    sgemm_k<128, 128, 8, 8, 8, 1, false><<<gH, 256>>>(F1, HFD, nullptr, rw1, HFD, rb1, F2, HFD, HFD);
    dot_k<<<TBn / 8, 256>>>(F2, rw2, rb2, pre_rew);

    // 8) losses (reward_loss faithfully reproduces the broadcast-vs-action bug)
    reduce_sq_k<false><<<NBLK, 256>>>(obs,    pre_obs, TBn * OBSD, PART);
    reduce_sq_k<false><<<NBLK, 256>>>(action, pre_act, TBn * ACTD, PART + NBLK);
    reduce_sq_k<true ><<<NBLK, 256>>>(action, pre_rew, TBn * ACTD, PART + 2 * NBLK);
    finalize_k<<<1, 256>>>(PART, out);
}

// round 8
// speedup vs baseline: 1.2904x; 1.2904x over previous
#include <cuda_runtime.h>
#include <math.h>

// Problem dims
#define TT   512
#define BB   256
#define OBSD 128
#define ACTD 32
#define IND  160
#define HIDD 512
#define G3D  1536
#define HFD  512

static constexpr size_t TBn = (size_t)TT * BB;      // 131072
static constexpr int NBLK = 2048;                    // reduction blocks per sum

// -------- scratch (static device globals; no runtime allocation) ----------
__device__ float g_GI [TBn * G3D];   // [T*B, 1536] input-gate preacts
__device__ float g_GI0[BB  * G3D];   // step-0 preacts
__device__ float g_HS [TBn * HIDD];  // emitted hidden states
__device__ float g_part[3 * NBLK];   // loss partials

// grid-barrier state for the persistent recurrence kernel (zero-init at load;
// counter returns to 0 after every barrier, generation is read relatively).
__device__ unsigned g_rcnt;
__device__ unsigned g_rgen;

__device__ __forceinline__ float4 ldg4(const float* p) {
    return *reinterpret_cast<const float4*>(p);
}
__device__ __forceinline__ float sigmoidf_(float x) { return 1.f / (1.f + expf(-x)); }

// ---- packed fp32x2 helpers (sm_100+ PTX; ptxas never emits these itself) ----
__device__ __forceinline__ unsigned long long pk2(float lo, float hi) {
    unsigned long long r;
    asm("mov.b64 %0, {%1, %2};" : "=l"(r) : "f"(lo), "f"(hi));
    return r;
}
__device__ __forceinline__ void fma2(unsigned long long& d,
                                     unsigned long long a, unsigned long long b) {
    asm("fma.rn.f32x2 %0, %1, %2, %0;" : "+l"(d) : "l"(a), "l"(b));
}
__device__ __forceinline__ float2 upk2(unsigned long long v) {
    float2 f;
    asm("mov.b64 {%0, %1}, %2;" : "=f"(f.x), "=f"(f.y) : "l"(v));
    return f;
}

// ---------------------------------------------------------------------------
// Generic tiled SGEMM with f32x2 inner loop:
//   C[M,N] = act( A[M,K] @ W[N,K]^T + bias[N] )
//   CONCAT: A row m is [obs[m,0:128] ‖ action[m,0:32]]
//   ACTMODE: 0 = identity, 1 = ELU
// TN must be even. All dims are multiples of tile params at every call site.
// ---------------------------------------------------------------------------
template<int BM, int BN, int BK, int TM, int TN, int ACTMODE, bool CONCAT>
__global__ void __launch_bounds__((BM / TM) * (BN / TN))
sgemm_k(const float* __restrict__ A, int ldA,
        const float* __restrict__ A2,
        const float* __restrict__ W, int ldW,
        const float* __restrict__ bias,
        float* __restrict__ C, int ldC,
        int K)
{
    constexpr int NT = (BM / TM) * (BN / TN);
    constexpr int KQ = BK / 4;
    constexpr int TNP = TN / 2;

    __shared__ __align__(16) float As[BK][BM + 4];
    __shared__ __align__(16) float Ws[BK][BN + 4];

    const int tid = threadIdx.x;
    const int tx  = tid % (BN / TN);
    const int ty  = tid / (BN / TN);
    const int m0  = blockIdx.y * BM;
    const int n0  = blockIdx.x * BN;

    unsigned long long acc2[TM][TNP];
#pragma unroll
    for (int i = 0; i < TM; i++)
#pragma unroll
        for (int j = 0; j < TNP; j++) acc2[i][j] = 0ull;

    for (int k0 = 0; k0 < K; k0 += BK) {
        for (int i4 = tid; i4 < BM * KQ; i4 += NT) {
            int m = i4 / KQ, q = i4 % KQ;
            int kg = k0 + q * 4;
            float4 v;
            if (CONCAT) {
                if (kg < OBSD) v = ldg4(A  + (size_t)(m0 + m) * OBSD + kg);
                else           v = ldg4(A2 + (size_t)(m0 + m) * ACTD + (kg - OBSD));
            } else {
                v = ldg4(A + (size_t)(m0 + m) * ldA + kg);
            }
            As[q * 4 + 0][m] = v.x; As[q * 4 + 1][m] = v.y;
            As[q * 4 + 2][m] = v.z; As[q * 4 + 3][m] = v.w;
        }
        for (int i4 = tid; i4 < BN * KQ; i4 += NT) {
            int n = i4 / KQ, q = i4 % KQ;
            int kg = k0 + q * 4;
            float4 v = ldg4(W + (size_t)(n0 + n) * ldW + kg);
            Ws[q * 4 + 0][n] = v.x; Ws[q * 4 + 1][n] = v.y;
            Ws[q * 4 + 2][n] = v.z; Ws[q * 4 + 3][n] = v.w;
        }
        __syncthreads();

#pragma unroll
        for (int kk = 0; kk < BK; kk++) {
            float a[TM];
#pragma unroll
            for (int i = 0; i < TM; i += 4)
                *reinterpret_cast<float4*>(&a[i]) =
                    *reinterpret_cast<const float4*>(&As[kk][ty * TM + i]);
            unsigned long long b2[TNP];
#pragma unroll
            for (int j = 0; j < TNP; j += 2) {
                ulonglong2 t = *reinterpret_cast<const ulonglong2*>(&Ws[kk][tx * TN + 2 * j]);
                b2[j] = t.x; b2[j + 1] = t.y;
            }
#pragma unroll
            for (int i = 0; i < TM; i++) {
                unsigned long long ad = pk2(a[i], a[i]);
#pragma unroll
                for (int j = 0; j < TNP; j++) fma2(acc2[i][j], ad, b2[j]);
            }
        }
        __syncthreads();
    }

#pragma unroll
    for (int i = 0; i < TM; i++) {
        size_t m = (size_t)m0 + ty * TM + i;
#pragma unroll
        for (int j = 0; j < TNP; j++) {
            float2 v2 = upk2(acc2[i][j]);
            int n = n0 + tx * TN + 2 * j;
            float v = v2.x + bias[n];
            float w = v2.y + bias[n + 1];
            if (ACTMODE == 1) {
                v = (v > 0.f) ? v : expm1f(v);
                w = (w > 0.f) ? w : expm1f(w);
            }
            C[m * (size_t)ldC + n]     = v;
            C[m * (size_t)ldC + n + 1] = w;
        }
    }
}

// ---------------------------------------------------------------------------
// Persistent GRU recurrence: ONE kernel runs all 511 steps.
// 128 CTAs (<=148 SMs, all co-resident), 256 threads each.
//   CTA (cg, bg): output slice = batch rows [bg*64, +64) x gate cols [cg*16, +16)
//   w_hh slice (3 gates x 16 cols x 512 K = 96KB) lives in smem for the WHOLE
//   kernel. h_t is staged in double-buffered smem chunks. Steps are separated
//   by a software grid barrier (all CTAs resident -> deadlock-free).
// Thread tile: 2 rows x 2 cols x 3 gates, accumulated as f32x2 column pairs.
// ---------------------------------------------------------------------------
#define RNCTA 128
#define RJC   16            // gate cols per CTA
#define RJS   18            // smem stride for W (padded)
#define RBR   64            // batch rows per CTA
#define RCHK  64            // K chunk
#define RAS   68            // smem stride for A chunk rows (64 + 4)

__device__ __forceinline__ void rnn_load_chunk(float* __restrict__ dst,
                                               const float* __restrict__ hp,
                                               int b0, int c, int tid)
{
#pragma unroll
    for (int p = 0; p < 4; p++) {
        int i4 = p * 256 + tid;
        int row = i4 >> 4, q = i4 & 15;
        float4 v = ldg4(hp + (size_t)(b0 + row) * HIDD + c * RCHK + q * 4);
        *reinterpret_cast<float4*>(&dst[row * RAS + q * 4]) = v;
    }
}

__global__ void __launch_bounds__(256, 1)
rnn_k(const float* __restrict__ w_hh, const float* __restrict__ b_hh,
      const float* __restrict__ gi_all, float* __restrict__ hs)
{
    extern __shared__ float sm[];
    float* Wsm = sm;                         // 3*512*RJS = 27648 floats
    float* A0  = sm + 3 * 512 * RJS;         // 64*68 = 4352 floats
    float* A1  = A0 + RCHK * RAS;            // second buffer

    const int tid = threadIdx.x;
    const int cg  = blockIdx.x & 31;         // 32 col groups
    const int bg  = blockIdx.x >> 5;         // 4 batch groups
    const int j0  = cg * RJC;
    const int b0  = bg * RBR;
    const int tx  = tid & 7;                 // 8 col-pairs
    const int ty  = tid >> 3;                // 32 row-pairs

    // one-time: load this CTA's w_hh slice into smem, transposed to [g][k][col]
    for (int i4 = tid; i4 < 48 * 128; i4 += 256) {
        int r = i4 >> 7, q = i4 & 127;
        int g = r >> 4, col = r & 15;
        float4 v = ldg4(w_hh + (size_t)(g * HIDD + j0 + col) * HIDD + q * 4);
        Wsm[(g * 512 + q * 4 + 0) * RJS + col] = v.x;
        Wsm[(g * 512 + q * 4 + 1) * RJS + col] = v.y;
        Wsm[(g * 512 + q * 4 + 2) * RJS + col] = v.z;
        Wsm[(g * 512 + q * 4 + 3) * RJS + col] = v.w;
    }
    float brr[2], bzz[2], bnn[2];
#pragma unroll
    for (int cc = 0; cc < 2; cc++) {
        int jg = j0 + 2 * tx + cc;
        brr[cc] = b_hh[jg]; bzz[cc] = b_hh[512 + jg]; bnn[cc] = b_hh[1024 + jg];
    }
    __syncthreads();

    for (int t = 0; t < TT - 1; t++) {
        const float* hp = hs + (size_t)t * BB * HIDD;
        float*       ho = hs + (size_t)(t + 1) * BB * HIDD;
        const float* gi = gi_all + (size_t)t * BB * G3D;

        unsigned long long ar2[2] = {0ull, 0ull};
        unsigned long long az2[2] = {0ull, 0ull};
        unsigned long long an2[2] = {0ull, 0ull};

        rnn_load_chunk(A0, hp, b0, 0, tid);
        __syncthreads();
#pragma unroll 1
        for (int c = 0; c < 8; c++) {
            float* Ac = (c & 1) ? A1 : A0;
            if (c < 7) rnn_load_chunk((c & 1) ? A0 : A1, hp, b0, c + 1, tid);
            const int kbase = c * RCHK;
#pragma unroll 16
            for (int kk = 0; kk < RCHK; kk++) {
                int kg = kbase + kk;
                float a0 = Ac[(2 * ty)     * RAS + kk];
                float a1 = Ac[(2 * ty + 1) * RAS + kk];
                unsigned long long wr2 = *reinterpret_cast<const unsigned long long*>(
                    &Wsm[(0 * 512 + kg) * RJS + 2 * tx]);
                unsigned long long wz2 = *reinterpret_cast<const unsigned long long*>(
                    &Wsm[(1 * 512 + kg) * RJS + 2 * tx]);
                unsigned long long wn2 = *reinterpret_cast<const unsigned long long*>(
                    &Wsm[(2 * 512 + kg) * RJS + 2 * tx]);
                unsigned long long ad0 = pk2(a0, a0);
                unsigned long long ad1 = pk2(a1, a1);
                fma2(ar2[0], ad0, wr2); fma2(ar2[1], ad1, wr2);
                fma2(az2[0], ad0, wz2); fma2(az2[1], ad1, wz2);
                fma2(an2[0], ad0, wn2); fma2(an2[1], ad1, wn2);
            }
            __syncthreads();
        }

        // gate math + store this CTA's [64 x 16] slice of h_{t+1}
#pragma unroll
        for (int rr = 0; rr < 2; rr++) {
            int m = b0 + 2 * ty + rr;
            const float* gim = gi + (size_t)m * G3D;
            float2 vr = upk2(ar2[rr]);
            float2 vz = upk2(az2[rr]);
            float2 vn = upk2(an2[rr]);
            float arv[2] = {vr.x, vr.y}, azv[2] = {vz.x, vz.y}, anv[2] = {vn.x, vn.y};
#pragma unroll
            for (int cc = 0; cc < 2; cc++) {
                int jg = j0 + 2 * tx + cc;
                float r = sigmoidf_(gim[jg]        + arv[cc] + brr[cc]);
                float z = sigmoidf_(gim[jg + 512]  + azv[cc] + bzz[cc]);
                float n = tanhf    (gim[jg + 1024] + r * (anv[cc] + bnn[cc]));
                ho[(size_t)m * HIDD + jg] =
                    (1.f - z) * n + z * hp[(size_t)m * HIDD + jg];
            }
        }

        // ---- grid barrier (generation-counting; all CTAs resident) ----
        __threadfence();
        __syncthreads();
        if (tid == 0) {
            unsigned g = *(volatile unsigned*)&g_rgen;
            __threadfence();
            unsigned a = atomicAdd(&g_rcnt, 1u);
            if (a == RNCTA - 1) {
                atomicExch(&g_rcnt, 0u);
                __threadfence();
                *(volatile unsigned*)&g_rgen = g + 1;
            } else {
                while (*(volatile unsigned*)&g_rgen == g) __nanosleep(32);
            }
        }
        __syncthreads();
    }
}

// step 0: h_prev = 0  =>  gh = b_hh,  h0 = (1-z)*n
__global__ void gate0_k(const float* __restrict__ gi, const float* __restrict__ bhh,
                        float* __restrict__ ho)
{
    int idx = blockIdx.x * blockDim.x + threadIdx.x;
    int b = idx >> 9, j = idx & 511;
    size_t base = (size_t)b * G3D + j;
    float r = sigmoidf_(gi[base]        + bhh[j]);
    float z = sigmoidf_(gi[base + 512]  + bhh[512 + j]);
    float n = tanhf    (gi[base + 1024] + r * bhh[1024 + j]);
    ho[idx] = (1.f - z) * n;
}

// ---------------------------------------------------------------------------
// N=1 head: pre_reward[m] = dot(F2[m,:], rw2) + rb2.  One warp per row.
// ---------------------------------------------------------------------------
__global__ void dot_k(const float* __restrict__ A, const float* __restrict__ w,
                      const float* __restrict__ bp, float* __restrict__ out)
{
    int g = blockIdx.x * blockDim.x + threadIdx.x;
    int row = g >> 5, lane = g & 31;
    const float4* a4 = reinterpret_cast<const float4*>(A + (size_t)row * HFD);
    const float4* w4 = reinterpret_cast<const float4*>(w);
    float s = 0.f;
#pragma unroll
    for (int i = lane; i < HFD / 4; i += 32) {
        float4 a = a4[i], b = w4[i];
        s += a.x * b.x + a.y * b.y + a.z * b.z + a.w * b.w;
    }
#pragma unroll
    for (int o = 16; o; o >>= 1) s += __shfl_xor_sync(0xffffffffu, s, o);
    if (lane == 0) out[row] = s + bp[0];
}

// ---------------------------------------------------------------------------
// Loss: deterministic 2-stage sum of squared residuals.
// BCAST: mu is [T*B,1] broadcast over the last (ACT=32) axis of x.
// ---------------------------------------------------------------------------
template<bool BCAST>
__global__ void reduce_sq_k(const float* __restrict__ x, const float* __restrict__ mu,
                            size_t n, float* __restrict__ part)
{
    float s = 0.f;
    for (size_t i = (size_t)blockIdx.x * blockDim.x + threadIdx.x; i < n;
         i += (size_t)gridDim.x * blockDim.x) {
        float m = BCAST ? mu[i >> 5] : mu[i];
        float d = x[i] - m;
        s += d * d;
    }
    __shared__ float sm[256];
    sm[threadIdx.x] = s; __syncthreads();
    for (int o = 128; o; o >>= 1) {
        if (threadIdx.x < o) sm[threadIdx.x] += sm[threadIdx.x + o];
        __syncthreads();
    }
    if (threadIdx.x == 0) part[blockIdx.x] = sm[0];
}

__global__ void finalize_k(const float* __restrict__ part, float* __restrict__ out)
{
    __shared__ double sm[256];
    double s = 0.0;
    for (int i = threadIdx.x; i < 3 * NBLK; i += 256) s += (double)part[i];
    sm[threadIdx.x] = s; __syncthreads();
    for (int o = 128; o; o >>= 1) {
        if (threadIdx.x < o) sm[threadIdx.x] += sm[threadIdx.x + o];
        __syncthreads();
    }
    if (threadIdx.x == 0) {
        const double LOG2PI = 1.8378770664093453;
        out[0] = (float)(0.5 * sm[0] / (double)(TT * BB)
                         + 0.5 * LOG2PI * (double)(OBSD + 2 * ACTD));
    }
}

// ---------------------------------------------------------------------------
extern "C" void kernel_launch(void* const* d_in, const int* in_sizes, int n_in,
                              void* d_out, int out_size)
{
    const float* obs    = (const float*)d_in[0];
    const float* action = (const float*)d_in[1];
    /* d_in[2] reward: unused by the reference math */
    const float* w_ih = (const float*)d_in[3];
    const float* w_hh = (const float*)d_in[4];
    const float* b_ih = (const float*)d_in[5];
    const float* b_hh = (const float*)d_in[6];
    const float* ow0 = (const float*)d_in[7],  *ob0 = (const float*)d_in[8];
    const float* ow1 = (const float*)d_in[9],  *ob1 = (const float*)d_in[10];
    const float* ow2 = (const float*)d_in[11], *ob2 = (const float*)d_in[12];
    const float* aw0 = (const float*)d_in[13], *ab0 = (const float*)d_in[14];
    const float* aw1 = (const float*)d_in[15], *ab1 = (const float*)d_in[16];
    const float* aw2 = (const float*)d_in[17], *ab2 = (const float*)d_in[18];
    const float* rw0 = (const float*)d_in[19], *rb0 = (const float*)d_in[20];
    const float* rw1 = (const float*)d_in[21], *rb1 = (const float*)d_in[22];
    const float* rw2 = (const float*)d_in[23], *rb2 = (const float*)d_in[24];

    float *GI, *GI0, *HS, *PART;
    cudaGetSymbolAddress((void**)&GI,   g_GI);
    cudaGetSymbolAddress((void**)&GI0,  g_GI0);
    cudaGetSymbolAddress((void**)&HS,   g_HS);
    cudaGetSymbolAddress((void**)&PART, g_part);
    // MLP scratch aliases the (dead after the recurrence) GI buffer.
    float* F1 = GI;
    float* F2 = GI + TBn * HFD;

    float* out      = (float*)d_out;
    float* pre_obs  = out + 1;
    float* pre_act  = pre_obs + TBn * OBSD;
    float* pre_rew  = pre_act + TBn * ACTD;

    // persistent kernel needs >48KB dynamic smem
    const int rnn_smem = (3 * 512 * RJS + 2 * RCHK * RAS) * (int)sizeof(float);
    cudaFuncSetAttribute(rnn_k, cudaFuncAttributeMaxDynamicSharedMemorySize, rnn_smem);

    // 1) GI = [obs‖action] @ w_ih^T + b_ih   for all T*B rows
    sgemm_k<128, 128, 8, 8, 8, 0, true><<<dim3(G3D / 128, TBn / 128), 256>>>(
        obs, 0, action, w_ih, IND, b_ih, GI, G3D, IND);

    // 2) GI0 = obs[0] @ w_ih[:, :128]^T + b_ih  (action part of x0 is zero)
    sgemm_k<64, 64, 8, 4, 4, 0, false><<<dim3(G3D / 64, BB / 64), 256>>>(
        obs, OBSD, nullptr, w_ih, IND, b_ih, GI0, G3D, OBSD);

    // 3) h0 (gh == b_hh since h_prev == 0) -> HS[0]
    gate0_k<<<(BB * HIDD) / 256, 256>>>(GI0, b_hh, HS);

    // 4) recurrence: ONE persistent kernel, all 511 steps
    rnn_k<<<RNCTA, 256, rnn_smem>>>(w_hh, b_hh, GI, HS);

    dim3 gH(HFD / 128, TBn / 128);
    dim3 gO(OBSD / 128, TBn / 128);
    dim3 gA(ACTD / 32, TBn / 128);

    // 5) obs head
    sgemm_k<128, 128, 8, 8, 8, 1, false><<<gH, 256>>>(HS, HIDD, nullptr, ow0, HIDD, ob0, F1, HFD, HIDD);
    sgemm_k<128, 128, 8, 8, 8, 1, false><<<gH, 256>>>(F1, HFD, nullptr, ow1, HFD, ob1, F2, HFD, HFD);
    sgemm_k<128, 128, 8, 8, 8, 0, false><<<gO, 256>>>(F2, HFD, nullptr, ow2, HFD, ob2, pre_obs, OBSD, HFD);

    // 6) action head (stop_gradient is identity in forward)
    sgemm_k<128, 128, 8, 8, 8, 1, false><<<gH, 256>>>(HS, HIDD, nullptr, aw0, HIDD, ab0, F1, HFD, HIDD);
    sgemm_k<128, 128, 8, 8, 8, 1, false><<<gH, 256>>>(F1, HFD, nullptr, aw1, HFD, ab1, F2, HFD, HFD);
    sgemm_k<128, 32, 8, 8, 4, 0, false><<<gA, 128>>>(F2, HFD, nullptr, aw2, HFD, ab2, pre_act, ACTD, HFD);

    // 7) reward head
    sgemm_k<128, 128, 8, 8, 8, 1, false><<<gH, 256>>>(HS, HIDD, nullptr, rw0, HIDD, rb0, F1, HFD, HIDD);
    sgemm_k<128, 128, 8, 8, 8, 1, false><<<gH, 256>>>(F1, HFD, nullptr, rw1, HFD, rb1, F2, HFD, HFD);
    dot_k<<<TBn / 8, 256>>>(F2, rw2, rb2, pre_rew);

    // 8) losses (reward_loss faithfully reproduces the broadcast-vs-action bug)
    reduce_sq_k<false><<<NBLK, 256>>>(obs,    pre_obs, TBn * OBSD, PART);
    reduce_sq_k<false><<<NBLK, 256>>>(action, pre_act, TBn * ACTD, PART + NBLK);
    reduce_sq_k<true ><<<NBLK, 256>>>(action, pre_rew, TBn * ACTD, PART + 2 * NBLK);
    finalize_k<<<1, 256>>>(PART, out);
}